// round 2
// baseline (speedup 1.0000x reference)
#include <cuda_runtime.h>
#include <cstdint>

#define BATCH 2048
#define IN 256
#define OUT 256
#define OT 16   // outputs per block
#define BT 16   // batches per block

// Single fused kernel:
//  - derives folded coefficients c1 = m*a2*a0, c0 = m*(a2*a1+a3) in registers
//  - computes postacts tile + y reduction
//  - stores postacts via TMA bulk stores (SMEM -> GMEM), bypassing the L1tex
//    per-thread store path that capped DRAM at 77% in R1.
__global__ __launch_bounds__(256) void kan_fused(const float* __restrict__ x,
                                                 const float4* __restrict__ affine,
                                                 const float* __restrict__ mask,
                                                 float* __restrict__ y,
                                                 float* __restrict__ post) {
    __shared__ float4 xs[BT * (IN / 4)];                   // 16 KB x tile
    __shared__ alignas(128) float4 ob[2][OT * (IN / 4)];   // 2 x 16 KB staging

    const int t = threadIdx.x;
    const int o_loc = t >> 4;        // 0..15
    const int lane = t & 15;         // 0..15
    const int o = blockIdx.y * OT + o_loc;
    const int b0 = blockIdx.x * BT;

    // ---- derive this thread's 16 (c1, c0) coefficients from affine/mask ----
    float4 c1r[4], c0r[4];
#pragma unroll
    for (int k = 0; k < 4; k++) {
        const int f = lane + 16 * k;            // float4 index within row (0..63)
        float4 m4 = reinterpret_cast<const float4*>(mask)[o * (IN / 4) + f];
        float mm[4] = {m4.x, m4.y, m4.z, m4.w};
        float c1v[4], c0v[4];
#pragma unroll
        for (int j = 0; j < 4; j++) {
            float4 a = affine[o * IN + 4 * f + j];   // (a0,a1,a2,a3)
            c1v[j] = mm[j] * a.z * a.x;
            c0v[j] = mm[j] * fmaf(a.z, a.y, a.w);
        }
        c1r[k] = make_float4(c1v[0], c1v[1], c1v[2], c1v[3]);
        c0r[k] = make_float4(c0v[0], c0v[1], c0v[2], c0v[3]);
    }

    // ---- cooperative load of the x tile (1024 float4s) ----
    const float4* xg = reinterpret_cast<const float4*>(x + (size_t)b0 * IN);
#pragma unroll
    for (int j = 0; j < 4; j++) xs[t + 256 * j] = xg[t + 256 * j];
    __syncthreads();

    // ---- main loop: one 16 KB contiguous chunk (16 output rows) per batch ----
    for (int bl = 0; bl < BT; bl++) {
        float4* buf = ob[bl & 1];

        if (bl >= 2) {
            // recycle staging buffer: ensure the copy issued 2 iterations ago
            // has finished READING smem (writes may still be in flight).
            if (t == 0)
                asm volatile("cp.async.bulk.wait_group.read 1;" ::: "memory");
            __syncthreads();
        }

        float acc = 0.0f;
#pragma unroll
        for (int k = 0; k < 4; k++) {
            float4 xv = xs[bl * (IN / 4) + lane + 16 * k];
            float4 p;
            p.x = fmaf(c1r[k].x, xv.x, c0r[k].x);
            p.y = fmaf(c1r[k].y, xv.y, c0r[k].y);
            p.z = fmaf(c1r[k].z, xv.z, c0r[k].z);
            p.w = fmaf(c1r[k].w, xv.w, c0r[k].w);
            acc += (p.x + p.y) + (p.z + p.w);
            buf[o_loc * (IN / 4) + lane + 16 * k] = p;
        }

        // y reduction across the 16 lanes sharing this output
#pragma unroll
        for (int off = 8; off; off >>= 1)
            acc += __shfl_xor_sync(0xffffffffu, acc, off);
        if (lane == 0) y[(size_t)(b0 + bl) * OUT + o] = acc;

        __syncthreads();

        if (t == 0) {
            // order generic-proxy smem writes before the async-proxy bulk read
            asm volatile("fence.proxy.async.shared::cta;" ::: "memory");
            float* dst = post + ((size_t)(b0 + bl) * OUT + (size_t)blockIdx.y * OT) * IN;
            uint32_t saddr = (uint32_t)__cvta_generic_to_shared(buf);
            asm volatile(
                "cp.async.bulk.global.shared::cta.bulk_group [%0], [%1], %2;"
                :: "l"(dst), "r"(saddr), "n"(OT * IN * 4) : "memory");
            asm volatile("cp.async.bulk.commit_group;" ::: "memory");
        }
    }
    // Pending bulk stores complete before kernel completion is visible; no tail
    // wait needed for correctness of subsequent launches/verification.
}

extern "C" void kernel_launch(void* const* d_in, const int* in_sizes, int n_in,
                              void* d_out, int out_size) {
    const float*  x      = (const float*)d_in[0];   // [2048, 256]
    const float4* affine = (const float4*)d_in[1];  // [256, 256, 4]
    const float*  mask   = (const float*)d_in[2];   // [256, 256]

    float* y    = (float*)d_out;                        // [2048, 256]
    float* post = (float*)d_out + (size_t)BATCH * OUT;  // [2048, 256, 256]

    dim3 grid(BATCH / BT, OUT / OT);
    kan_fused<<<grid, 256>>>(x, affine, mask, y, post);
}